// round 6
// baseline (speedup 1.0000x reference)
#include <cuda_runtime.h>
#include <cuda_bf16.h>

#define N_NODES 100000
#define N_EDGES 1600000
#define F 128
#define H 128
#define NB_SCAN ((N_NODES + 255) / 256)   // 391

// Scratch (__device__ globals; no cudaMalloc allowed).
__device__ int   g_deg[2 * N_NODES];           // [0,N)=deg_out, [N,2N)=deg_in
__device__ float g_rs_out[N_NODES];
__device__ float g_rs_in[N_NODES];
__device__ int   g_esrc[N_EDGES];              // src ids sorted by dst
__device__ int   g_rowtmp[N_NODES];
__device__ int   g_blksum[512];
__device__ int   g_blkoff[512];
__device__ int   g_row_start[N_NODES];
__device__ int   g_cursor[N_NODES];

// ---------------------------------------------------------------------------
// K1: degree histograms (4 edges/thread, int4 loads).
// ---------------------------------------------------------------------------
__global__ void deg_kernel(const int* __restrict__ src, const int* __restrict__ dst,
                           int n_edges) {
    int i4 = blockIdx.x * blockDim.x + threadIdx.x;
    int base = i4 * 4;
    if (base + 3 < n_edges) {
        int4 s = reinterpret_cast<const int4*>(src)[i4];
        int4 d = reinterpret_cast<const int4*>(dst)[i4];
        atomicAdd(&g_deg[s.x], 1); atomicAdd(&g_deg[s.y], 1);
        atomicAdd(&g_deg[s.z], 1); atomicAdd(&g_deg[s.w], 1);
        atomicAdd(&g_deg[N_NODES + d.x], 1); atomicAdd(&g_deg[N_NODES + d.y], 1);
        atomicAdd(&g_deg[N_NODES + d.z], 1); atomicAdd(&g_deg[N_NODES + d.w], 1);
    } else {
        for (int e = base; e < n_edges; ++e) {
            atomicAdd(&g_deg[src[e]], 1);
            atomicAdd(&g_deg[N_NODES + dst[e]], 1);
        }
    }
}

// ---------------------------------------------------------------------------
// Scan (3 kernels): exclusive prefix sum of deg_in -> row_start/cursor;
// scan_add also materializes rsqrt scale arrays.
// ---------------------------------------------------------------------------
__global__ void scan_block_kernel() {
    __shared__ int sm[256];
    const int tid = threadIdx.x;
    const int i = blockIdx.x * 256 + tid;
    int v = (i < N_NODES) ? g_deg[N_NODES + i] : 0;
    sm[tid] = v;
    __syncthreads();
    #pragma unroll
    for (int off = 1; off < 256; off <<= 1) {
        int t = (tid >= off) ? sm[tid - off] : 0;
        __syncthreads();
        sm[tid] += t;
        __syncthreads();
    }
    if (i < N_NODES) g_rowtmp[i] = sm[tid] - v;
    if (tid == 255) g_blksum[blockIdx.x] = sm[255];
}

__global__ void scan_top_kernel() {
    __shared__ int sm[512];
    const int tid = threadIdx.x;  // 512
    int v = (tid < NB_SCAN) ? g_blksum[tid] : 0;
    sm[tid] = v;
    __syncthreads();
    #pragma unroll
    for (int off = 1; off < 512; off <<= 1) {
        int t = (tid >= off) ? sm[tid - off] : 0;
        __syncthreads();
        sm[tid] += t;
        __syncthreads();
    }
    g_blkoff[tid] = sm[tid] - v;
}

__global__ void scan_add_kernel() {
    int i = blockIdx.x * blockDim.x + threadIdx.x;
    if (i < N_NODES) {
        int base = g_rowtmp[i] + g_blkoff[i >> 8];
        g_row_start[i] = base;
        g_cursor[i]    = base;
        g_rs_out[i] = rsqrtf(fmaxf((float)g_deg[i], 1.0f));
        g_rs_in[i]  = rsqrtf(fmaxf((float)g_deg[N_NODES + i], 1.0f));
    }
}

// ---------------------------------------------------------------------------
// Scatter: counting-sort src ids by dst (4 edges/thread, int4 loads).
// ---------------------------------------------------------------------------
__global__ void scatter_kernel(const int* __restrict__ src, const int* __restrict__ dst,
                               int n_edges) {
    int i4 = blockIdx.x * blockDim.x + threadIdx.x;
    int base = i4 * 4;
    if (base + 3 < n_edges) {
        int4 s = reinterpret_cast<const int4*>(src)[i4];
        int4 d = reinterpret_cast<const int4*>(dst)[i4];
        g_esrc[atomicAdd(&g_cursor[d.x], 1)] = s.x;
        g_esrc[atomicAdd(&g_cursor[d.y], 1)] = s.y;
        g_esrc[atomicAdd(&g_cursor[d.z], 1)] = s.z;
        g_esrc[atomicAdd(&g_cursor[d.w], 1)] = s.w;
    } else {
        for (int e = base; e < n_edges; ++e)
            g_esrc[atomicAdd(&g_cursor[dst[e]], 1)] = src[e];
    }
}

// ---------------------------------------------------------------------------
// Fused: CSR aggregation (gather into smem A tile) + GEMM + bias + relu.
//
// smem: Ws [128][128] f32, chunk-PERMUTED rows (even 16B chunks first, then
//       odd) so warp-wide W reads are 256B contiguous (conflict-free);
//       As2 [128][128] float2, A duplicated {a,a} for direct f32x2 use.
// 256 threads. Gather: warp w handles rows w, w+8, ... (16 rows), lane =
// float4 slice; edge loop unrolled x4 for MLP. Mainloop: 8x8 micro-tile,
// f32x2 FMA (4 FFMA2 per LDS.128 -> FMA-bound).
// ---------------------------------------------------------------------------
#define FMA_F32X2(d, a, b) \
    asm("fma.rn.f32x2 %0, %1, %2, %0;" : "+l"(d) : "l"(a), "l"(b))
#define UNPACK_F32X2(lo, hi, in) \
    asm("mov.b64 {%0, %1}, %2;" : "=f"(lo), "=f"(hi) : "l"(in))

__global__ void __launch_bounds__(256, 1)
fused_agg_gemm_kernel(const float* __restrict__ X,
                      const float* __restrict__ Wm,
                      const float* __restrict__ bias,
                      float* __restrict__ out) {
    extern __shared__ float smem[];
    float*  Ws  = smem;                                        // [128][128] permuted
    float2* As2 = reinterpret_cast<float2*>(smem + 128 * 128); // [128][128] dup

    const int tid  = threadIdx.x;
    const int lane = tid & 31;
    const int wrp  = tid >> 5;          // 0..7
    const int row0 = blockIdx.x * 128;

    // ---- Stage W with chunk permutation: logical chunk c -> (c>>1)|((c&1)<<4)
    for (int i = tid; i < 128 * 32; i += 256) {
        const int k = i >> 5;
        const int c = i & 31;
        const int p = (c >> 1) | ((c & 1) << 4);
        reinterpret_cast<float4*>(Ws)[k * 32 + p] =
            reinterpret_cast<const float4*>(Wm)[i];
    }

    // ---- Gather phase: aggregate dst rows directly into As2 (dup format).
    const float4* X4 = reinterpret_cast<const float4*>(X);
    for (int t = 0; t < 16; ++t) {
        const int rl  = wrp + t * 8;        // local row 0..127
        const int row = row0 + rl;
        float4 acc = make_float4(0.f, 0.f, 0.f, 0.f);
        if (row < N_NODES) {
            const int start = g_row_start[row];
            const int n     = g_deg[N_NODES + row];
            for (int b = 0; b < n; b += 32) {
                const int m = min(n - b, 32);
                int s = 0; float sc = 0.0f;
                if (lane < m) {
                    s  = g_esrc[start + b + lane];   // coalesced
                    sc = g_rs_out[s];                // random, L2-resident
                }
                int i = 0;
                for (; i + 4 <= m; i += 4) {         // 4 independent loads in flight
                    const int   s0 = __shfl_sync(0xffffffffu, s, i);
                    const int   s1 = __shfl_sync(0xffffffffu, s, i + 1);
                    const int   s2 = __shfl_sync(0xffffffffu, s, i + 2);
                    const int   s3 = __shfl_sync(0xffffffffu, s, i + 3);
                    const float f0 = __shfl_sync(0xffffffffu, sc, i);
                    const float f1 = __shfl_sync(0xffffffffu, sc, i + 1);
                    const float f2 = __shfl_sync(0xffffffffu, sc, i + 2);
                    const float f3 = __shfl_sync(0xffffffffu, sc, i + 3);
                    const float4 v0 = X4[(size_t)s0 * 32 + lane];
                    const float4 v1 = X4[(size_t)s1 * 32 + lane];
                    const float4 v2 = X4[(size_t)s2 * 32 + lane];
                    const float4 v3 = X4[(size_t)s3 * 32 + lane];
                    acc.x += v0.x * f0; acc.y += v0.y * f0;
                    acc.z += v0.z * f0; acc.w += v0.w * f0;
                    acc.x += v1.x * f1; acc.y += v1.y * f1;
                    acc.z += v1.z * f1; acc.w += v1.w * f1;
                    acc.x += v2.x * f2; acc.y += v2.y * f2;
                    acc.z += v2.z * f2; acc.w += v2.w * f2;
                    acc.x += v3.x * f3; acc.y += v3.y * f3;
                    acc.z += v3.z * f3; acc.w += v3.w * f3;
                }
                for (; i < m; ++i) {
                    const int   ss = __shfl_sync(0xffffffffu, s, i);
                    const float sf = __shfl_sync(0xffffffffu, sc, i);
                    const float4 v = X4[(size_t)ss * 32 + lane];
                    acc.x += v.x * sf; acc.y += v.y * sf;
                    acc.z += v.z * sf; acc.w += v.w * sf;
                }
            }
            const float ri = g_rs_in[row];
            acc.x *= ri; acc.y *= ri; acc.z *= ri; acc.w *= ri;
        }
        // Write duplicated: float2 idx [4*lane .. 4*lane+4) of row rl.
        float4* dp = reinterpret_cast<float4*>(As2 + rl * 128) + lane * 2;
        dp[0] = make_float4(acc.x, acc.x, acc.y, acc.y);
        dp[1] = make_float4(acc.z, acc.z, acc.w, acc.w);
    }
    __syncthreads();

    // ---- GEMM mainloop: 8x8 micro-tile per thread.
    const int cg = tid & 15;    // cols [8cg, 8cg+8)
    const int rg = tid >> 4;    // rows [8rg, 8rg+8)

    unsigned long long acc[8][4];
    #pragma unroll
    for (int j = 0; j < 8; ++j)
        #pragma unroll
        for (int c = 0; c < 4; ++c) acc[j][c] = 0ull;

    const float*  wbase = Ws + cg * 4;            // permuted: even chunks at +0
    const float2* abase = As2 + (rg * 8) * 128;

    #pragma unroll 4
    for (int k = 0; k < 128; k += 2) {
        // logical floats [8cg,8cg+8) of rows k,k+1 via permuted layout:
        // wA = chunk 2cg -> phys float offset cg*4 ; wB = chunk 2cg+1 -> 64+cg*4
        const ulonglong2 wA = *reinterpret_cast<const ulonglong2*>(wbase + k * 128);
        const ulonglong2 wB = *reinterpret_cast<const ulonglong2*>(wbase + k * 128 + 64);
        const ulonglong2 wC = *reinterpret_cast<const ulonglong2*>(wbase + (k + 1) * 128);
        const ulonglong2 wD = *reinterpret_cast<const ulonglong2*>(wbase + (k + 1) * 128 + 64);
        #pragma unroll
        for (int j = 0; j < 8; ++j) {
            const ulonglong2 aa =
                *reinterpret_cast<const ulonglong2*>(abase + j * 128 + k);
            FMA_F32X2(acc[j][0], aa.x, wA.x);
            FMA_F32X2(acc[j][1], aa.x, wA.y);
            FMA_F32X2(acc[j][2], aa.x, wB.x);
            FMA_F32X2(acc[j][3], aa.x, wB.y);
            FMA_F32X2(acc[j][0], aa.y, wC.x);
            FMA_F32X2(acc[j][1], aa.y, wC.y);
            FMA_F32X2(acc[j][2], aa.y, wD.x);
            FMA_F32X2(acc[j][3], aa.y, wD.y);
        }
    }

    const float4 b0 = reinterpret_cast<const float4*>(bias)[cg * 2];
    const float4 b1 = reinterpret_cast<const float4*>(bias)[cg * 2 + 1];
    #pragma unroll
    for (int j = 0; j < 8; ++j) {
        const int row = row0 + rg * 8 + j;
        if (row < N_NODES) {
            float c0, c1, c2, c3, c4, c5, c6, c7;
            UNPACK_F32X2(c0, c1, acc[j][0]);
            UNPACK_F32X2(c2, c3, acc[j][1]);
            UNPACK_F32X2(c4, c5, acc[j][2]);
            UNPACK_F32X2(c6, c7, acc[j][3]);
            float4 o0, o1;
            o0.x = fmaxf(c0 + b0.x, 0.f); o0.y = fmaxf(c1 + b0.y, 0.f);
            o0.z = fmaxf(c2 + b0.z, 0.f); o0.w = fmaxf(c3 + b0.w, 0.f);
            o1.x = fmaxf(c4 + b1.x, 0.f); o1.y = fmaxf(c5 + b1.y, 0.f);
            o1.z = fmaxf(c6 + b1.z, 0.f); o1.w = fmaxf(c7 + b1.w, 0.f);
            float4* op = reinterpret_cast<float4*>(out + (size_t)row * H) + cg * 2;
            op[0] = o0;
            op[1] = o1;
        }
    }
}

// ---------------------------------------------------------------------------
// launch
// ---------------------------------------------------------------------------
extern "C" void kernel_launch(void* const* d_in, const int* in_sizes, int n_in,
                              void* d_out, int out_size) {
    const float* X    = (const float*)d_in[0];
    const int*   src  = (const int*)d_in[1];
    const int*   dst  = (const int*)d_in[2];
    const float* Wm   = (const float*)d_in[3];
    const float* bias = (const float*)d_in[4];
    float*       out  = (float*)d_out;

    const int n_edges = in_sizes[1];

    void* dg = nullptr;
    cudaGetSymbolAddress(&dg, g_deg);
    cudaMemsetAsync(dg, 0, sizeof(int) * 2 * N_NODES, 0);

    deg_kernel<<<(n_edges / 4 + 255) / 256 + 1, 256>>>(src, dst, n_edges);
    scan_block_kernel<<<NB_SCAN, 256>>>();
    scan_top_kernel<<<1, 512>>>();
    scan_add_kernel<<<(N_NODES + 255) / 256, 256>>>();
    scatter_kernel<<<(n_edges / 4 + 255) / 256 + 1, 256>>>(src, dst, n_edges);
    {
        const int smem_bytes = (128 * 128 + 2 * 128 * 128) * (int)sizeof(float); // 192KB
        cudaFuncSetAttribute(fused_agg_gemm_kernel,
                             cudaFuncAttributeMaxDynamicSharedMemorySize, smem_bytes);
        fused_agg_gemm_kernel<<<(N_NODES + 127) / 128, 256, smem_bytes>>>(X, Wm, bias, out);
    }
}

// round 11
// speedup vs baseline: 1.3506x; 1.3506x over previous
#include <cuda_runtime.h>
#include <cuda_bf16.h>

#define N_NODES 100000
#define N_EDGES 1600000
#define F 128
#define H 128
#define NB_SCAN ((N_NODES + 255) / 256)   // 391

// Scratch (__device__ globals; no cudaMalloc allowed).
__device__ float g_agg[(size_t)N_NODES * F];   // normalized aggregation (rs_in folded)
__device__ int   g_deg[2 * N_NODES];           // [0,N)=deg_out, [N,2N)=deg_in
__device__ float g_rs_out[N_NODES];
__device__ float g_rs_in[N_NODES];
__device__ int   g_esrc[N_EDGES];              // src ids sorted by dst
__device__ int   g_rowtmp[N_NODES];
__device__ int   g_blksum[512];
__device__ int   g_blkoff[512];
__device__ int   g_row_start[N_NODES];
__device__ int   g_cursor[N_NODES];

// ---------------------------------------------------------------------------
// K1: degree histograms (4 edges/thread, int4 loads).
// ---------------------------------------------------------------------------
__global__ void deg_kernel(const int* __restrict__ src, const int* __restrict__ dst,
                           int n_edges) {
    int i4 = blockIdx.x * blockDim.x + threadIdx.x;
    int base = i4 * 4;
    if (base + 3 < n_edges) {
        int4 s = reinterpret_cast<const int4*>(src)[i4];
        int4 d = reinterpret_cast<const int4*>(dst)[i4];
        atomicAdd(&g_deg[s.x], 1); atomicAdd(&g_deg[s.y], 1);
        atomicAdd(&g_deg[s.z], 1); atomicAdd(&g_deg[s.w], 1);
        atomicAdd(&g_deg[N_NODES + d.x], 1); atomicAdd(&g_deg[N_NODES + d.y], 1);
        atomicAdd(&g_deg[N_NODES + d.z], 1); atomicAdd(&g_deg[N_NODES + d.w], 1);
    } else {
        for (int e = base; e < n_edges; ++e) {
            atomicAdd(&g_deg[src[e]], 1);
            atomicAdd(&g_deg[N_NODES + dst[e]], 1);
        }
    }
}

// ---------------------------------------------------------------------------
// Scan (3 kernels): exclusive prefix sum of deg_in -> row_start/cursor;
// scan_add also materializes rsqrt scale arrays.
// ---------------------------------------------------------------------------
__global__ void scan_block_kernel() {
    __shared__ int sm[256];
    const int tid = threadIdx.x;
    const int i = blockIdx.x * 256 + tid;
    int v = (i < N_NODES) ? g_deg[N_NODES + i] : 0;
    sm[tid] = v;
    __syncthreads();
    #pragma unroll
    for (int off = 1; off < 256; off <<= 1) {
        int t = (tid >= off) ? sm[tid - off] : 0;
        __syncthreads();
        sm[tid] += t;
        __syncthreads();
    }
    if (i < N_NODES) g_rowtmp[i] = sm[tid] - v;
    if (tid == 255) g_blksum[blockIdx.x] = sm[255];
}

__global__ void scan_top_kernel() {
    __shared__ int sm[512];
    const int tid = threadIdx.x;  // 512
    int v = (tid < NB_SCAN) ? g_blksum[tid] : 0;
    sm[tid] = v;
    __syncthreads();
    #pragma unroll
    for (int off = 1; off < 512; off <<= 1) {
        int t = (tid >= off) ? sm[tid - off] : 0;
        __syncthreads();
        sm[tid] += t;
        __syncthreads();
    }
    g_blkoff[tid] = sm[tid] - v;
}

__global__ void scan_add_kernel() {
    int i = blockIdx.x * blockDim.x + threadIdx.x;
    if (i < N_NODES) {
        int base = g_rowtmp[i] + g_blkoff[i >> 8];
        g_row_start[i] = base;
        g_cursor[i]    = base;
        g_rs_out[i] = rsqrtf(fmaxf((float)g_deg[i], 1.0f));
        g_rs_in[i]  = rsqrtf(fmaxf((float)g_deg[N_NODES + i], 1.0f));
    }
}

// ---------------------------------------------------------------------------
// Scatter: counting-sort src ids by dst (4 edges/thread, int4 loads).
// ---------------------------------------------------------------------------
__global__ void scatter_kernel(const int* __restrict__ src, const int* __restrict__ dst,
                               int n_edges) {
    int i4 = blockIdx.x * blockDim.x + threadIdx.x;
    int base = i4 * 4;
    if (base + 3 < n_edges) {
        int4 s = reinterpret_cast<const int4*>(src)[i4];
        int4 d = reinterpret_cast<const int4*>(dst)[i4];
        g_esrc[atomicAdd(&g_cursor[d.x], 1)] = s.x;
        g_esrc[atomicAdd(&g_cursor[d.y], 1)] = s.y;
        g_esrc[atomicAdd(&g_cursor[d.z], 1)] = s.z;
        g_esrc[atomicAdd(&g_cursor[d.w], 1)] = s.w;
    } else {
        for (int e = base; e < n_edges; ++e)
            g_esrc[atomicAdd(&g_cursor[dst[e]], 1)] = src[e];
    }
}

// ---------------------------------------------------------------------------
// K2: CSR aggregation at FULL occupancy. One warp per dst node; lane = float4
// slice. x4-unrolled inner loop -> 4 independent LDG.128 chains per warp.
//   g_agg[d] = rs_in[d] * sum_{s in N(d)} X[s] * rs_out[s]
// ---------------------------------------------------------------------------
__global__ void agg_csr_kernel(const float* __restrict__ X) {
    const int warp = (blockIdx.x * blockDim.x + threadIdx.x) >> 5;
    if (warp >= N_NODES) return;
    const int lane  = threadIdx.x & 31;
    const int start = g_row_start[warp];
    const int n     = g_deg[N_NODES + warp];

    const float4* X4 = reinterpret_cast<const float4*>(X);
    float4 acc = make_float4(0.f, 0.f, 0.f, 0.f);
    for (int b = 0; b < n; b += 32) {
        const int m = min(n - b, 32);
        int s = 0; float sc = 0.0f;
        if (lane < m) {
            s  = g_esrc[start + b + lane];   // coalesced
            sc = g_rs_out[s];                // random, L2-resident (400KB)
        }
        int i = 0;
        for (; i + 4 <= m; i += 4) {         // 4 independent loads in flight
            const int   s0 = __shfl_sync(0xffffffffu, s, i);
            const int   s1 = __shfl_sync(0xffffffffu, s, i + 1);
            const int   s2 = __shfl_sync(0xffffffffu, s, i + 2);
            const int   s3 = __shfl_sync(0xffffffffu, s, i + 3);
            const float f0 = __shfl_sync(0xffffffffu, sc, i);
            const float f1 = __shfl_sync(0xffffffffu, sc, i + 1);
            const float f2 = __shfl_sync(0xffffffffu, sc, i + 2);
            const float f3 = __shfl_sync(0xffffffffu, sc, i + 3);
            const float4 v0 = X4[(size_t)s0 * 32 + lane];
            const float4 v1 = X4[(size_t)s1 * 32 + lane];
            const float4 v2 = X4[(size_t)s2 * 32 + lane];
            const float4 v3 = X4[(size_t)s3 * 32 + lane];
            acc.x += v0.x * f0; acc.y += v0.y * f0;
            acc.z += v0.z * f0; acc.w += v0.w * f0;
            acc.x += v1.x * f1; acc.y += v1.y * f1;
            acc.z += v1.z * f1; acc.w += v1.w * f1;
            acc.x += v2.x * f2; acc.y += v2.y * f2;
            acc.z += v2.z * f2; acc.w += v2.w * f2;
            acc.x += v3.x * f3; acc.y += v3.y * f3;
            acc.z += v3.z * f3; acc.w += v3.w * f3;
        }
        for (; i < m; ++i) {
            const int   ss = __shfl_sync(0xffffffffu, s, i);
            const float sf = __shfl_sync(0xffffffffu, sc, i);
            const float4 v = X4[(size_t)ss * 32 + lane];
            acc.x += v.x * sf; acc.y += v.y * sf;
            acc.z += v.z * sf; acc.w += v.w * sf;
        }
    }
    const float ri = g_rs_in[warp];
    acc.x *= ri; acc.y *= ri; acc.z *= ri; acc.w *= ri;
    reinterpret_cast<float4*>(g_agg + (size_t)warp * F)[lane] = acc;
}

// ---------------------------------------------------------------------------
// K3: GEMM + bias + relu. 128x128 tile, 8x8 micro-tile, f32x2 FMA.
// Ws chunk-PERMUTED (even 16B chunks first) -> warp W reads 256B contiguous,
// conflict-free. As2 duplicated {a,a}. 256 threads, occ=1 (192KB smem).
// ---------------------------------------------------------------------------
#define FMA_F32X2(d, a, b) \
    asm("fma.rn.f32x2 %0, %1, %2, %0;" : "+l"(d) : "l"(a), "l"(b))
#define UNPACK_F32X2(lo, hi, in) \
    asm("mov.b64 {%0, %1}, %2;" : "=f"(lo), "=f"(hi) : "l"(in))

__global__ void __launch_bounds__(256, 1)
gemm_kernel(const float* __restrict__ Wm,
            const float* __restrict__ bias,
            float* __restrict__ out) {
    extern __shared__ float smem[];
    float*  Ws  = smem;                                        // [128][128] permuted
    float2* As2 = reinterpret_cast<float2*>(smem + 128 * 128); // [128][128] dup

    const int tid  = threadIdx.x;
    const int row0 = blockIdx.x * 128;

    // Stage W with chunk permutation: logical chunk c -> (c>>1)|((c&1)<<4)
    for (int i = tid; i < 128 * 32; i += 256) {
        const int k = i >> 5;
        const int c = i & 31;
        const int p = (c >> 1) | ((c & 1) << 4);
        reinterpret_cast<float4*>(Ws)[k * 32 + p] =
            reinterpret_cast<const float4*>(Wm)[i];
    }

    // Stage A tile duplicated {a,a} from g_agg (L2-resident).
    for (int i = tid; i < 128 * 32; i += 256) {
        const int r   = i >> 5;
        const int c   = i & 31;
        const int row = row0 + r;
        float4 v = make_float4(0.f, 0.f, 0.f, 0.f);
        if (row < N_NODES)
            v = reinterpret_cast<const float4*>(g_agg + (size_t)row * F)[c];
        float2* dp = As2 + r * 128 + c * 4;
        dp[0] = make_float2(v.x, v.x);
        dp[1] = make_float2(v.y, v.y);
        dp[2] = make_float2(v.z, v.z);
        dp[3] = make_float2(v.w, v.w);
    }
    __syncthreads();

    const int cg = tid & 15;    // cols [8cg, 8cg+8)
    const int rg = tid >> 4;    // rows [8rg, 8rg+8)

    unsigned long long acc[8][4];
    #pragma unroll
    for (int j = 0; j < 8; ++j)
        #pragma unroll
        for (int c = 0; c < 4; ++c) acc[j][c] = 0ull;

    const float*  wbase = Ws + cg * 4;            // permuted: even chunks at +0
    const float2* abase = As2 + (rg * 8) * 128;

    #pragma unroll 4
    for (int k = 0; k < 128; k += 2) {
        // logical floats [8cg,8cg+8) of rows k,k+1 via permuted layout
        const ulonglong2 wA = *reinterpret_cast<const ulonglong2*>(wbase + k * 128);
        const ulonglong2 wB = *reinterpret_cast<const ulonglong2*>(wbase + k * 128 + 64);
        const ulonglong2 wC = *reinterpret_cast<const ulonglong2*>(wbase + (k + 1) * 128);
        const ulonglong2 wD = *reinterpret_cast<const ulonglong2*>(wbase + (k + 1) * 128 + 64);
        #pragma unroll
        for (int j = 0; j < 8; ++j) {
            const ulonglong2 aa =
                *reinterpret_cast<const ulonglong2*>(abase + j * 128 + k);
            FMA_F32X2(acc[j][0], aa.x, wA.x);
            FMA_F32X2(acc[j][1], aa.x, wA.y);
            FMA_F32X2(acc[j][2], aa.x, wB.x);
            FMA_F32X2(acc[j][3], aa.x, wB.y);
            FMA_F32X2(acc[j][0], aa.y, wC.x);
            FMA_F32X2(acc[j][1], aa.y, wC.y);
            FMA_F32X2(acc[j][2], aa.y, wD.x);
            FMA_F32X2(acc[j][3], aa.y, wD.y);
        }
    }

    const float4 b0 = reinterpret_cast<const float4*>(bias)[cg * 2];
    const float4 b1 = reinterpret_cast<const float4*>(bias)[cg * 2 + 1];
    #pragma unroll
    for (int j = 0; j < 8; ++j) {
        const int row = row0 + rg * 8 + j;
        if (row < N_NODES) {
            float c0, c1, c2, c3, c4, c5, c6, c7;
            UNPACK_F32X2(c0, c1, acc[j][0]);
            UNPACK_F32X2(c2, c3, acc[j][1]);
            UNPACK_F32X2(c4, c5, acc[j][2]);
            UNPACK_F32X2(c6, c7, acc[j][3]);
            float4 o0, o1;
            o0.x = fmaxf(c0 + b0.x, 0.f); o0.y = fmaxf(c1 + b0.y, 0.f);
            o0.z = fmaxf(c2 + b0.z, 0.f); o0.w = fmaxf(c3 + b0.w, 0.f);
            o1.x = fmaxf(c4 + b1.x, 0.f); o1.y = fmaxf(c5 + b1.y, 0.f);
            o1.z = fmaxf(c6 + b1.z, 0.f); o1.w = fmaxf(c7 + b1.w, 0.f);
            float4* op = reinterpret_cast<float4*>(out + (size_t)row * H) + cg * 2;
            op[0] = o0;
            op[1] = o1;
        }
    }
}

// ---------------------------------------------------------------------------
// launch
// ---------------------------------------------------------------------------
extern "C" void kernel_launch(void* const* d_in, const int* in_sizes, int n_in,
                              void* d_out, int out_size) {
    const float* X    = (const float*)d_in[0];
    const int*   src  = (const int*)d_in[1];
    const int*   dst  = (const int*)d_in[2];
    const float* Wm   = (const float*)d_in[3];
    const float* bias = (const float*)d_in[4];
    float*       out  = (float*)d_out;

    const int n_edges = in_sizes[1];

    void* dg = nullptr;
    cudaGetSymbolAddress(&dg, g_deg);
    cudaMemsetAsync(dg, 0, sizeof(int) * 2 * N_NODES, 0);

    deg_kernel<<<(n_edges / 4 + 255) / 256 + 1, 256>>>(src, dst, n_edges);
    scan_block_kernel<<<NB_SCAN, 256>>>();
    scan_top_kernel<<<1, 512>>>();
    scan_add_kernel<<<(N_NODES + 255) / 256, 256>>>();
    scatter_kernel<<<(n_edges / 4 + 255) / 256 + 1, 256>>>(src, dst, n_edges);
    agg_csr_kernel<<<(N_NODES * 32 + 255) / 256, 256>>>(X);
    {
        const int smem_bytes = (128 * 128 + 2 * 128 * 128) * (int)sizeof(float); // 192KB
        cudaFuncSetAttribute(gemm_kernel,
                             cudaFuncAttributeMaxDynamicSharedMemorySize, smem_bytes);
        gemm_kernel<<<(N_NODES + 127) / 128, 256, smem_bytes>>>(Wm, bias, out);
    }
}

// round 15
// speedup vs baseline: 2.1076x; 1.5605x over previous
#include <cuda_runtime.h>
#include <cuda_bf16.h>
#include <cstdint>

#define N_NODES 100000
#define N_EDGES 1600000
#define F 128
#define H 128
#define NB_SCAN ((N_NODES + 255) / 256)   // 391

// Scratch (__device__ globals; no cudaMalloc allowed).
__device__ float g_agg[(size_t)N_NODES * F];   // normalized aggregation (rs_in folded)
__device__ int   g_deg[2 * N_NODES];           // [0,N)=deg_out, [N,2N)=deg_in
__device__ float g_rs_out[N_NODES];
__device__ float g_rs_in[N_NODES];
__device__ int   g_esrc[N_EDGES];              // src ids sorted by dst
__device__ int   g_rowtmp[N_NODES];
__device__ int   g_blksum[512];
__device__ int   g_blkoff[512];
__device__ int   g_row_start[N_NODES];
__device__ int   g_cursor[N_NODES];
// W^T split hi/lo: [n][k] row-major bf16 (128x128 each).
__device__ __nv_bfloat16 g_wt_hi[128 * 128];
__device__ __nv_bfloat16 g_wt_lo[128 * 128];

// ---------------------------------------------------------------------------
// K1: degree histograms (4 edges/thread, int4 loads).
// ---------------------------------------------------------------------------
__global__ void deg_kernel(const int* __restrict__ src, const int* __restrict__ dst,
                           int n_edges) {
    int i4 = blockIdx.x * blockDim.x + threadIdx.x;
    int base = i4 * 4;
    if (base + 3 < n_edges) {
        int4 s = reinterpret_cast<const int4*>(src)[i4];
        int4 d = reinterpret_cast<const int4*>(dst)[i4];
        atomicAdd(&g_deg[s.x], 1); atomicAdd(&g_deg[s.y], 1);
        atomicAdd(&g_deg[s.z], 1); atomicAdd(&g_deg[s.w], 1);
        atomicAdd(&g_deg[N_NODES + d.x], 1); atomicAdd(&g_deg[N_NODES + d.y], 1);
        atomicAdd(&g_deg[N_NODES + d.z], 1); atomicAdd(&g_deg[N_NODES + d.w], 1);
    } else {
        for (int e = base; e < n_edges; ++e) {
            atomicAdd(&g_deg[src[e]], 1);
            atomicAdd(&g_deg[N_NODES + dst[e]], 1);
        }
    }
}

// ---------------------------------------------------------------------------
// W prep: W^T[n][k] = W[k][n], split into bf16 hi + lo, row-major [n][k].
// ---------------------------------------------------------------------------
__global__ void wprep_kernel(const float* __restrict__ Wm) {
    int i = blockIdx.x * blockDim.x + threadIdx.x;   // i = n*128 + k
    if (i < 128 * 128) {
        const int n = i >> 7;
        const int k = i & 127;
        const float w = Wm[k * 128 + n];
        const __nv_bfloat16 hi = __float2bfloat16(w);
        const __nv_bfloat16 lo = __float2bfloat16(w - __bfloat162float(hi));
        g_wt_hi[i] = hi;
        g_wt_lo[i] = lo;
    }
}

// ---------------------------------------------------------------------------
// Scan (3 kernels): exclusive prefix sum of deg_in -> row_start/cursor;
// scan_add also materializes rsqrt scale arrays.
// ---------------------------------------------------------------------------
__global__ void scan_block_kernel() {
    __shared__ int sm[256];
    const int tid = threadIdx.x;
    const int i = blockIdx.x * 256 + tid;
    int v = (i < N_NODES) ? g_deg[N_NODES + i] : 0;
    sm[tid] = v;
    __syncthreads();
    #pragma unroll
    for (int off = 1; off < 256; off <<= 1) {
        int t = (tid >= off) ? sm[tid - off] : 0;
        __syncthreads();
        sm[tid] += t;
        __syncthreads();
    }
    if (i < N_NODES) g_rowtmp[i] = sm[tid] - v;
    if (tid == 255) g_blksum[blockIdx.x] = sm[255];
}

__global__ void scan_top_kernel() {
    __shared__ int sm[512];
    const int tid = threadIdx.x;  // 512
    int v = (tid < NB_SCAN) ? g_blksum[tid] : 0;
    sm[tid] = v;
    __syncthreads();
    #pragma unroll
    for (int off = 1; off < 512; off <<= 1) {
        int t = (tid >= off) ? sm[tid - off] : 0;
        __syncthreads();
        sm[tid] += t;
        __syncthreads();
    }
    g_blkoff[tid] = sm[tid] - v;
}

__global__ void scan_add_kernel() {
    int i = blockIdx.x * blockDim.x + threadIdx.x;
    if (i < N_NODES) {
        int base = g_rowtmp[i] + g_blkoff[i >> 8];
        g_row_start[i] = base;
        g_cursor[i]    = base;
        g_rs_out[i] = rsqrtf(fmaxf((float)g_deg[i], 1.0f));
        g_rs_in[i]  = rsqrtf(fmaxf((float)g_deg[N_NODES + i], 1.0f));
    }
}

// ---------------------------------------------------------------------------
// Scatter: counting-sort src ids by dst (4 edges/thread, int4 loads).
// ---------------------------------------------------------------------------
__global__ void scatter_kernel(const int* __restrict__ src, const int* __restrict__ dst,
                               int n_edges) {
    int i4 = blockIdx.x * blockDim.x + threadIdx.x;
    int base = i4 * 4;
    if (base + 3 < n_edges) {
        int4 s = reinterpret_cast<const int4*>(src)[i4];
        int4 d = reinterpret_cast<const int4*>(dst)[i4];
        g_esrc[atomicAdd(&g_cursor[d.x], 1)] = s.x;
        g_esrc[atomicAdd(&g_cursor[d.y], 1)] = s.y;
        g_esrc[atomicAdd(&g_cursor[d.z], 1)] = s.z;
        g_esrc[atomicAdd(&g_cursor[d.w], 1)] = s.w;
    } else {
        for (int e = base; e < n_edges; ++e)
            g_esrc[atomicAdd(&g_cursor[dst[e]], 1)] = src[e];
    }
}

// ---------------------------------------------------------------------------
// K2: CSR aggregation at FULL occupancy (unchanged from 290us kernel).
// ---------------------------------------------------------------------------
__global__ void agg_csr_kernel(const float* __restrict__ X) {
    const int warp = (blockIdx.x * blockDim.x + threadIdx.x) >> 5;
    if (warp >= N_NODES) return;
    const int lane  = threadIdx.x & 31;
    const int start = g_row_start[warp];
    const int n     = g_deg[N_NODES + warp];

    const float4* X4 = reinterpret_cast<const float4*>(X);
    float4 acc = make_float4(0.f, 0.f, 0.f, 0.f);
    for (int b = 0; b < n; b += 32) {
        const int m = min(n - b, 32);
        int s = 0; float sc = 0.0f;
        if (lane < m) {
            s  = g_esrc[start + b + lane];
            sc = g_rs_out[s];
        }
        int i = 0;
        for (; i + 4 <= m; i += 4) {
            const int   s0 = __shfl_sync(0xffffffffu, s, i);
            const int   s1 = __shfl_sync(0xffffffffu, s, i + 1);
            const int   s2 = __shfl_sync(0xffffffffu, s, i + 2);
            const int   s3 = __shfl_sync(0xffffffffu, s, i + 3);
            const float f0 = __shfl_sync(0xffffffffu, sc, i);
            const float f1 = __shfl_sync(0xffffffffu, sc, i + 1);
            const float f2 = __shfl_sync(0xffffffffu, sc, i + 2);
            const float f3 = __shfl_sync(0xffffffffu, sc, i + 3);
            const float4 v0 = X4[(size_t)s0 * 32 + lane];
            const float4 v1 = X4[(size_t)s1 * 32 + lane];
            const float4 v2 = X4[(size_t)s2 * 32 + lane];
            const float4 v3 = X4[(size_t)s3 * 32 + lane];
            acc.x += v0.x * f0; acc.y += v0.y * f0;
            acc.z += v0.z * f0; acc.w += v0.w * f0;
            acc.x += v1.x * f1; acc.y += v1.y * f1;
            acc.z += v1.z * f1; acc.w += v1.w * f1;
            acc.x += v2.x * f2; acc.y += v2.y * f2;
            acc.z += v2.z * f2; acc.w += v2.w * f2;
            acc.x += v3.x * f3; acc.y += v3.y * f3;
            acc.z += v3.z * f3; acc.w += v3.w * f3;
        }
        for (; i < m; ++i) {
            const int   ss = __shfl_sync(0xffffffffu, s, i);
            const float sf = __shfl_sync(0xffffffffu, sc, i);
            const float4 v = X4[(size_t)ss * 32 + lane];
            acc.x += v.x * sf; acc.y += v.y * sf;
            acc.z += v.z * sf; acc.w += v.w * sf;
        }
    }
    const float ri = g_rs_in[warp];
    acc.x *= ri; acc.y *= ri; acc.z *= ri; acc.w *= ri;
    reinterpret_cast<float4*>(g_agg + (size_t)warp * F)[lane] = acc;
}

// ---------------------------------------------------------------------------
// K3: mma.sync bf16 split-precision GEMM + bias + relu (base sm_100 path).
//   out = relu( A @ W + b ).  A,W split hi/lo bf16; 3 passes Ah*Wh + Ah*Wl
//   + Al*Wh with fp32 accumulators -> ~1e-5 rel err.
// A fragments loaded as float2 straight from L2-resident g_agg (no A smem).
// W^T hi/lo staged in smem with 272B row stride (bank = 4g+t -> conflict-free).
// 256 threads, warp wr covers rows [16wr,16wr+16); 16 n-tiles x 8 k-steps.
// smem = 68KB -> 3 CTAs/SM.
// ---------------------------------------------------------------------------
#define BSTRIDE 272   // bytes per W^T row in smem (16B aligned, conflict-free)

#define MMA_BF16(c, a, b0, b1)                                              \
    asm volatile(                                                           \
        "mma.sync.aligned.m16n8k16.row.col.f32.bf16.bf16.f32 "              \
        "{%0,%1,%2,%3}, {%4,%5,%6,%7}, {%8,%9}, {%0,%1,%2,%3};"             \
        : "+f"((c)[0]), "+f"((c)[1]), "+f"((c)[2]), "+f"((c)[3])            \
        : "r"((a)[0]), "r"((a)[1]), "r"((a)[2]), "r"((a)[3]),               \
          "r"(b0), "r"(b1))

__device__ __forceinline__ void split_bf16x2(float2 v, uint32_t& hi, uint32_t& lo) {
    __nv_bfloat162 h = __floats2bfloat162_rn(v.x, v.y);
    __nv_bfloat162 l = __floats2bfloat162_rn(v.x - __bfloat162float(__low2bfloat16(h)),
                                             v.y - __bfloat162float(__high2bfloat16(h)));
    hi = *reinterpret_cast<uint32_t*>(&h);
    lo = *reinterpret_cast<uint32_t*>(&l);
}

__global__ void __launch_bounds__(256)
gemm_mma_kernel(const float* __restrict__ bias, float* __restrict__ out) {
    extern __shared__ char smem[];
    char* sh = smem;                       // W^T hi: 128 rows x 272B
    char* sl = smem + 128 * BSTRIDE;       // W^T lo

    const int tid  = threadIdx.x;
    const int lane = tid & 31;
    const int wr   = tid >> 5;     // warp 0..7
    const int g    = lane >> 2;    // 0..7
    const int t    = lane & 3;     // 0..3

    // Stage W^T hi/lo into padded smem rows (16B chunks, coalesced).
    {
        const int4* bh = reinterpret_cast<const int4*>(g_wt_hi);
        const int4* bl = reinterpret_cast<const int4*>(g_wt_lo);
        for (int i = tid; i < 128 * 16; i += 256) {   // 16 x 16B chunks per 256B row
            const int row = i >> 4;
            const int c   = i & 15;
            *reinterpret_cast<int4*>(sh + row * BSTRIDE + c * 16) = bh[i];
            *reinterpret_cast<int4*>(sl + row * BSTRIDE + c * 16) = bl[i];
        }
    }
    __syncthreads();

    const int rg  = blockIdx.x * 128 + wr * 16 + g;
    const int rg8 = rg + 8;
    const bool vg  = rg  < N_NODES;
    const bool vg8 = rg8 < N_NODES;
    const float2* Ag  = reinterpret_cast<const float2*>(g_agg + (size_t)rg  * F);
    const float2* Ag8 = reinterpret_cast<const float2*>(g_agg + (size_t)rg8 * F);

    // 16 n-tiles x 8 cols = 128 output columns.
    float c[16][4];
    #pragma unroll
    for (int nt = 0; nt < 16; ++nt)
        #pragma unroll
        for (int j = 0; j < 4; ++j) c[nt][j] = 0.0f;

    const float2 z2 = make_float2(0.f, 0.f);
    #pragma unroll
    for (int ks = 0; ks < 8; ++ks) {
        // A fragments: rows {g, g+8}, k cols {2t,2t+1} and {2t+8,2t+9}.
        const int f2i = ks * 8 + t;         // float2 index along k
        float2 x0 = vg  ? Ag [f2i]     : z2;
        float2 x1 = vg8 ? Ag8[f2i]     : z2;
        float2 x2 = vg  ? Ag [f2i + 4] : z2;
        float2 x3 = vg8 ? Ag8[f2i + 4] : z2;
        uint32_t ah[4], al[4];
        split_bf16x2(x0, ah[0], al[0]);
        split_bf16x2(x1, ah[1], al[1]);
        split_bf16x2(x2, ah[2], al[2]);
        split_bf16x2(x3, ah[3], al[3]);

        const int boff = (ks * 16 + 2 * t) * 2;   // byte offset along k
        #pragma unroll
        for (int nt = 0; nt < 16; ++nt) {
            const char* ph = sh + (nt * 8 + g) * BSTRIDE + boff;
            const char* pl = sl + (nt * 8 + g) * BSTRIDE + boff;
            const uint32_t b0h = *reinterpret_cast<const uint32_t*>(ph);
            const uint32_t b1h = *reinterpret_cast<const uint32_t*>(ph + 16);
            const uint32_t b0l = *reinterpret_cast<const uint32_t*>(pl);
            const uint32_t b1l = *reinterpret_cast<const uint32_t*>(pl + 16);
            MMA_BF16(c[nt], ah, b0h, b1h);
            MMA_BF16(c[nt], ah, b0l, b1l);
            MMA_BF16(c[nt], al, b0h, b1h);
        }
    }

    // Epilogue: c0,c1 -> (rg, col..col+1); c2,c3 -> (rg8, ...), +bias, relu.
    #pragma unroll
    for (int nt = 0; nt < 16; ++nt) {
        const int col = nt * 8 + 2 * t;
        const float2 b2 = *reinterpret_cast<const float2*>(bias + col);
        if (vg) {
            float2 o;
            o.x = fmaxf(c[nt][0] + b2.x, 0.f);
            o.y = fmaxf(c[nt][1] + b2.y, 0.f);
            *reinterpret_cast<float2*>(out + (size_t)rg * H + col) = o;
        }
        if (vg8) {
            float2 o;
            o.x = fmaxf(c[nt][2] + b2.x, 0.f);
            o.y = fmaxf(c[nt][3] + b2.y, 0.f);
            *reinterpret_cast<float2*>(out + (size_t)rg8 * H + col) = o;
        }
    }
}

// ---------------------------------------------------------------------------
// launch
// ---------------------------------------------------------------------------
extern "C" void kernel_launch(void* const* d_in, const int* in_sizes, int n_in,
                              void* d_out, int out_size) {
    const float* X    = (const float*)d_in[0];
    const int*   src  = (const int*)d_in[1];
    const int*   dst  = (const int*)d_in[2];
    const float* Wm   = (const float*)d_in[3];
    const float* bias = (const float*)d_in[4];
    float*       out  = (float*)d_out;

    const int n_edges = in_sizes[1];

    void* dg = nullptr;
    cudaGetSymbolAddress(&dg, g_deg);
    cudaMemsetAsync(dg, 0, sizeof(int) * 2 * N_NODES, 0);

    deg_kernel<<<(n_edges / 4 + 255) / 256 + 1, 256>>>(src, dst, n_edges);
    wprep_kernel<<<(128 * 128 + 255) / 256, 256>>>(Wm);
    scan_block_kernel<<<NB_SCAN, 256>>>();
    scan_top_kernel<<<1, 512>>>();
    scan_add_kernel<<<(N_NODES + 255) / 256, 256>>>();
    scatter_kernel<<<(n_edges / 4 + 255) / 256 + 1, 256>>>(src, dst, n_edges);
    agg_csr_kernel<<<(N_NODES * 32 + 255) / 256, 256>>>(X);
    {
        const int smem_bytes = 2 * 128 * BSTRIDE;   // 68KB
        cudaFuncSetAttribute(gemm_mma_kernel,
                             cudaFuncAttributeMaxDynamicSharedMemorySize, smem_bytes);
        gemm_mma_kernel<<<(N_NODES + 127) / 128, 256, smem_bytes>>>(bias, out);
    }
}

// round 16
// speedup vs baseline: 2.1311x; 1.0111x over previous
#include <cuda_runtime.h>
#include <cuda_bf16.h>
#include <cstdint>

#define N_NODES 100000
#define N_EDGES 1600000
#define F 128
#define H 128
#define NB_SCAN ((N_NODES + 255) / 256)   // 391

// Scratch (__device__ globals; no cudaMalloc allowed).
__device__ float g_agg[(size_t)N_NODES * F];   // normalized aggregation (rs_in folded)
__device__ int   g_deg[2 * N_NODES];           // [0,N)=deg_out, [N,2N)=deg_in
__device__ float g_rs_out[N_NODES];
__device__ float g_rs_in[N_NODES];
__device__ int   g_esrc[N_EDGES];              // src ids sorted by dst
__device__ int   g_rowtmp[N_NODES];
__device__ int   g_blksum[512];
__device__ int   g_row_start[N_NODES];
__device__ int   g_cursor[N_NODES];
// W^T hi/lo packed for single-LDS.128 B-fragments:
// per (n, ks, t) one 16B group = {hi(2t,2t+1), hi(2t+8,2t+9), lo(2t,2t+1), lo(2t+8,2t+9)}
// bf16 index = n*256 + ks*32 + t*8 + h*2 + (k&1), lo at +4.  (512B per n-row)
__device__ __nv_bfloat16 g_wtp[128 * 256];

// ---------------------------------------------------------------------------
// K1: degree histograms (4 edges/thread, int4 loads) + fused W prep.
// ---------------------------------------------------------------------------
__global__ void deg_wprep_kernel(const int* __restrict__ src, const int* __restrict__ dst,
                                 const float* __restrict__ Wm, int n_edges) {
    int i4 = blockIdx.x * blockDim.x + threadIdx.x;
    int base = i4 * 4;
    if (base + 3 < n_edges) {
        int4 s = reinterpret_cast<const int4*>(src)[i4];
        int4 d = reinterpret_cast<const int4*>(dst)[i4];
        atomicAdd(&g_deg[s.x], 1); atomicAdd(&g_deg[s.y], 1);
        atomicAdd(&g_deg[s.z], 1); atomicAdd(&g_deg[s.w], 1);
        atomicAdd(&g_deg[N_NODES + d.x], 1); atomicAdd(&g_deg[N_NODES + d.y], 1);
        atomicAdd(&g_deg[N_NODES + d.z], 1); atomicAdd(&g_deg[N_NODES + d.w], 1);
    } else {
        for (int e = base; e < n_edges; ++e) {
            atomicAdd(&g_deg[src[e]], 1);
            atomicAdd(&g_deg[N_NODES + dst[e]], 1);
        }
    }
    // Fused W prep: W^T[n][k] = W[k][n] -> hi/lo bf16, packed layout.
    if (i4 < 128 * 128) {
        const int n = i4 >> 7;
        const int k = i4 & 127;
        const float w = Wm[k * 128 + n];
        const __nv_bfloat16 hi = __float2bfloat16(w);
        const __nv_bfloat16 lo = __float2bfloat16(w - __bfloat162float(hi));
        const int ks = k >> 4;
        const int r  = k & 15;
        const int t  = (r & 7) >> 1;
        const int h  = r >> 3;
        const int idx = n * 256 + ks * 32 + t * 8 + h * 2 + (r & 1);
        g_wtp[idx]     = hi;
        g_wtp[idx + 4] = lo;
    }
}

// ---------------------------------------------------------------------------
// Scan (2 kernels): scan_block computes per-block prefixes + block sums;
// scan_add recomputes the block-sum prefix itself (<=390 adds), then emits
// row_start/cursor and rsqrt scale arrays.
// ---------------------------------------------------------------------------
__global__ void scan_block_kernel() {
    __shared__ int sm[256];
    const int tid = threadIdx.x;
    const int i = blockIdx.x * 256 + tid;
    int v = (i < N_NODES) ? g_deg[N_NODES + i] : 0;
    sm[tid] = v;
    __syncthreads();
    #pragma unroll
    for (int off = 1; off < 256; off <<= 1) {
        int t = (tid >= off) ? sm[tid - off] : 0;
        __syncthreads();
        sm[tid] += t;
        __syncthreads();
    }
    if (i < N_NODES) g_rowtmp[i] = sm[tid] - v;
    if (tid == 255) g_blksum[blockIdx.x] = sm[255];
}

__global__ void scan_add_kernel() {
    __shared__ int red[8];
    __shared__ int sbase;
    const int tid = threadIdx.x;
    const int b   = blockIdx.x;
    // block prefix: sum blksum[0..b)
    int part = 0;
    for (int j = tid; j < b; j += 256) part += g_blksum[j];
    #pragma unroll
    for (int o = 16; o; o >>= 1) part += __shfl_down_sync(0xffffffffu, part, o);
    if ((tid & 31) == 0) red[tid >> 5] = part;
    __syncthreads();
    if (tid == 0) {
        int s = 0;
        #pragma unroll
        for (int w = 0; w < 8; ++w) s += red[w];
        sbase = s;
    }
    __syncthreads();
    const int i = b * 256 + tid;
    if (i < N_NODES) {
        int rbase = g_rowtmp[i] + sbase;
        g_row_start[i] = rbase;
        g_cursor[i]    = rbase;
        g_rs_out[i] = rsqrtf(fmaxf((float)g_deg[i], 1.0f));
        g_rs_in[i]  = rsqrtf(fmaxf((float)g_deg[N_NODES + i], 1.0f));
    }
}

// ---------------------------------------------------------------------------
// Scatter: counting-sort src ids by dst (4 edges/thread, int4 loads).
// ---------------------------------------------------------------------------
__global__ void scatter_kernel(const int* __restrict__ src, const int* __restrict__ dst,
                               int n_edges) {
    int i4 = blockIdx.x * blockDim.x + threadIdx.x;
    int base = i4 * 4;
    if (base + 3 < n_edges) {
        int4 s = reinterpret_cast<const int4*>(src)[i4];
        int4 d = reinterpret_cast<const int4*>(dst)[i4];
        g_esrc[atomicAdd(&g_cursor[d.x], 1)] = s.x;
        g_esrc[atomicAdd(&g_cursor[d.y], 1)] = s.y;
        g_esrc[atomicAdd(&g_cursor[d.z], 1)] = s.z;
        g_esrc[atomicAdd(&g_cursor[d.w], 1)] = s.w;
    } else {
        for (int e = base; e < n_edges; ++e)
            g_esrc[atomicAdd(&g_cursor[dst[e]], 1)] = src[e];
    }
}

// ---------------------------------------------------------------------------
// K2: CSR aggregation at FULL occupancy (unchanged from 186us kernel).
// ---------------------------------------------------------------------------
__global__ void agg_csr_kernel(const float* __restrict__ X) {
    const int warp = (blockIdx.x * blockDim.x + threadIdx.x) >> 5;
    if (warp >= N_NODES) return;
    const int lane  = threadIdx.x & 31;
    const int start = g_row_start[warp];
    const int n     = g_deg[N_NODES + warp];

    const float4* X4 = reinterpret_cast<const float4*>(X);
    float4 acc = make_float4(0.f, 0.f, 0.f, 0.f);
    for (int b = 0; b < n; b += 32) {
        const int m = min(n - b, 32);
        int s = 0; float sc = 0.0f;
        if (lane < m) {
            s  = g_esrc[start + b + lane];
            sc = g_rs_out[s];
        }
        int i = 0;
        for (; i + 4 <= m; i += 4) {
            const int   s0 = __shfl_sync(0xffffffffu, s, i);
            const int   s1 = __shfl_sync(0xffffffffu, s, i + 1);
            const int   s2 = __shfl_sync(0xffffffffu, s, i + 2);
            const int   s3 = __shfl_sync(0xffffffffu, s, i + 3);
            const float f0 = __shfl_sync(0xffffffffu, sc, i);
            const float f1 = __shfl_sync(0xffffffffu, sc, i + 1);
            const float f2 = __shfl_sync(0xffffffffu, sc, i + 2);
            const float f3 = __shfl_sync(0xffffffffu, sc, i + 3);
            const float4 v0 = X4[(size_t)s0 * 32 + lane];
            const float4 v1 = X4[(size_t)s1 * 32 + lane];
            const float4 v2 = X4[(size_t)s2 * 32 + lane];
            const float4 v3 = X4[(size_t)s3 * 32 + lane];
            acc.x += v0.x * f0; acc.y += v0.y * f0;
            acc.z += v0.z * f0; acc.w += v0.w * f0;
            acc.x += v1.x * f1; acc.y += v1.y * f1;
            acc.z += v1.z * f1; acc.w += v1.w * f1;
            acc.x += v2.x * f2; acc.y += v2.y * f2;
            acc.z += v2.z * f2; acc.w += v2.w * f2;
            acc.x += v3.x * f3; acc.y += v3.y * f3;
            acc.z += v3.z * f3; acc.w += v3.w * f3;
        }
        for (; i < m; ++i) {
            const int   ss = __shfl_sync(0xffffffffu, s, i);
            const float sf = __shfl_sync(0xffffffffu, sc, i);
            const float4 v = X4[(size_t)ss * 32 + lane];
            acc.x += v.x * sf; acc.y += v.y * sf;
            acc.z += v.z * sf; acc.w += v.w * sf;
        }
    }
    const float ri = g_rs_in[warp];
    acc.x *= ri; acc.y *= ri; acc.z *= ri; acc.w *= ri;
    reinterpret_cast<float4*>(g_agg + (size_t)warp * F)[lane] = acc;
}

// ---------------------------------------------------------------------------
// K3: mma.sync bf16 split-precision GEMM + bias + relu.
// B fragments now come from ONE LDS.128 per (nt,ks): {b0h,b1h,b0l,b1l}.
// smem row stride 576B (144 words): phase lanes hit banks {0,4,8,12} /
// {16,20,24,28} alternating by g -> conflict-free.
// ---------------------------------------------------------------------------
#define WSTRIDE 576   // bytes per W^T packed row in smem

#define MMA_BF16(c, a, b0, b1)                                              \
    asm volatile(                                                           \
        "mma.sync.aligned.m16n8k16.row.col.f32.bf16.bf16.f32 "              \
        "{%0,%1,%2,%3}, {%4,%5,%6,%7}, {%8,%9}, {%0,%1,%2,%3};"             \
        : "+f"((c)[0]), "+f"((c)[1]), "+f"((c)[2]), "+f"((c)[3])            \
        : "r"((a)[0]), "r"((a)[1]), "r"((a)[2]), "r"((a)[3]),               \
          "r"(b0), "r"(b1))

__device__ __forceinline__ void split_bf16x2(float2 v, uint32_t& hi, uint32_t& lo) {
    __nv_bfloat162 h = __floats2bfloat162_rn(v.x, v.y);
    __nv_bfloat162 l = __floats2bfloat162_rn(v.x - __bfloat162float(__low2bfloat16(h)),
                                             v.y - __bfloat162float(__high2bfloat16(h)));
    hi = *reinterpret_cast<uint32_t*>(&h);
    lo = *reinterpret_cast<uint32_t*>(&l);
}

__global__ void __launch_bounds__(256)
gemm_mma_kernel(const float* __restrict__ bias, float* __restrict__ out) {
    extern __shared__ char smem[];

    const int tid  = threadIdx.x;
    const int lane = tid & 31;
    const int wr   = tid >> 5;     // warp 0..7
    const int g    = lane >> 2;    // 0..7
    const int t    = lane & 3;     // 0..3

    // Stage packed W (64KB) into 576B-stride smem rows (16B chunks, coalesced).
    {
        const int4* bp = reinterpret_cast<const int4*>(g_wtp);
        for (int i = tid; i < 4096; i += 256) {   // 32 x 16B chunks per 512B row
            const int row = i >> 5;
            const int c   = i & 31;
            *reinterpret_cast<int4*>(smem + row * WSTRIDE + c * 16) = bp[i];
        }
    }
    __syncthreads();

    const int rg  = blockIdx.x * 128 + wr * 16 + g;
    const int rg8 = rg + 8;
    const bool vg  = rg  < N_NODES;
    const bool vg8 = rg8 < N_NODES;
    const float2* Ag  = reinterpret_cast<const float2*>(g_agg + (size_t)rg  * F);
    const float2* Ag8 = reinterpret_cast<const float2*>(g_agg + (size_t)rg8 * F);

    // 16 n-tiles x 8 cols = 128 output columns.
    float c[16][4];
    #pragma unroll
    for (int nt = 0; nt < 16; ++nt)
        #pragma unroll
        for (int j = 0; j < 4; ++j) c[nt][j] = 0.0f;

    const char* bbase = smem + g * WSTRIDE + t * 16;
    const float2 z2 = make_float2(0.f, 0.f);
    #pragma unroll
    for (int ks = 0; ks < 8; ++ks) {
        // A fragments: rows {g, g+8}, k cols {2t,2t+1} and {2t+8,2t+9}.
        const int f2i = ks * 8 + t;         // float2 index along k
        float2 x0 = vg  ? Ag [f2i]     : z2;
        float2 x1 = vg8 ? Ag8[f2i]     : z2;
        float2 x2 = vg  ? Ag [f2i + 4] : z2;
        float2 x3 = vg8 ? Ag8[f2i + 4] : z2;
        uint32_t ah[4], al[4];
        split_bf16x2(x0, ah[0], al[0]);
        split_bf16x2(x1, ah[1], al[1]);
        split_bf16x2(x2, ah[2], al[2]);
        split_bf16x2(x3, ah[3], al[3]);

        const char* bks = bbase + ks * 64;
        #pragma unroll
        for (int nt = 0; nt < 16; ++nt) {
            const uint4 q = *reinterpret_cast<const uint4*>(bks + nt * 8 * WSTRIDE);
            MMA_BF16(c[nt], ah, q.x, q.y);   // Ah * Wh
            MMA_BF16(c[nt], ah, q.z, q.w);   // Ah * Wl
            MMA_BF16(c[nt], al, q.x, q.y);   // Al * Wh
        }
    }

    // Epilogue: c0,c1 -> (rg, col..col+1); c2,c3 -> (rg8, ...), +bias, relu.
    #pragma unroll
    for (int nt = 0; nt < 16; ++nt) {
        const int col = nt * 8 + 2 * t;
        const float2 b2 = *reinterpret_cast<const float2*>(bias + col);
        if (vg) {
            float2 o;
            o.x = fmaxf(c[nt][0] + b2.x, 0.f);
            o.y = fmaxf(c[nt][1] + b2.y, 0.f);
            *reinterpret_cast<float2*>(out + (size_t)rg * H + col) = o;
        }
        if (vg8) {
            float2 o;
            o.x = fmaxf(c[nt][2] + b2.x, 0.f);
            o.y = fmaxf(c[nt][3] + b2.y, 0.f);
            *reinterpret_cast<float2*>(out + (size_t)rg8 * H + col) = o;
        }
    }
}

// ---------------------------------------------------------------------------
// launch  (7 launches: memset, deg+wprep, scan_block, scan_add, scatter,
//          agg, gemm — ncu's sampled launch #5 is now scatter)
// ---------------------------------------------------------------------------
extern "C" void kernel_launch(void* const* d_in, const int* in_sizes, int n_in,
                              void* d_out, int out_size) {
    const float* X    = (const float*)d_in[0];
    const int*   src  = (const int*)d_in[1];
    const int*   dst  = (const int*)d_in[2];
    const float* Wm   = (const float*)d_in[3];
    const float* bias = (const float*)d_in[4];
    float*       out  = (float*)d_out;

    const int n_edges = in_sizes[1];

    void* dg = nullptr;
    cudaGetSymbolAddress(&dg, g_deg);
    cudaMemsetAsync(dg, 0, sizeof(int) * 2 * N_NODES, 0);

    deg_wprep_kernel<<<(n_edges / 4 + 255) / 256 + 1, 256>>>(src, dst, Wm, n_edges);
    scan_block_kernel<<<NB_SCAN, 256>>>();
    scan_add_kernel<<<NB_SCAN, 256>>>();
    scatter_kernel<<<(n_edges / 4 + 255) / 256 + 1, 256>>>(src, dst, n_edges);
    agg_csr_kernel<<<(N_NODES * 32 + 255) / 256, 256>>>(X);
    {
        const int smem_bytes = 128 * WSTRIDE;   // 72KB
        cudaFuncSetAttribute(gemm_mma_kernel,
                             cudaFuncAttributeMaxDynamicSharedMemorySize, smem_bytes);
        gemm_mma_kernel<<<(N_NODES + 127) / 128, 256, smem_bytes>>>(bias, out);
    }
}